// round 8
// baseline (speedup 1.0000x reference)
#include <cuda_runtime.h>
#include <cstdint>

// ---------------------------------------------------------------------------
// CustomOrientationLoss (R8):
//   pack:  (x,s) -> aligned float4 table, zero Z   [1 node/thr, full-chip grid]
//   edge:  symmetric per-edge scatter, red.v4.f32  [2 edges/thr, occ 6 — at LTS
//          sector floor: 2 gather + 2 RMW sectors/edge; proven in R7]
//   node:  cos/angle reduction + fused finalize    [1 node/thr, full-chip grid]
//
// R7 post-mortem: edge phase is LTS-sector-throughput bound (~52us ~= floor).
// Helper kernels had grid=98 (< 148 SMs) -> starved. Scalar-per-thread fixes it.
// ---------------------------------------------------------------------------

#define NMAX 100000

__device__ float4 g_P[NMAX];        // (x0,x1,x2,s)
__device__ float4 g_Z[NMAX];        // accumulator (w unused)
__device__ double g_acc[3];         // sum(1-|cos|), sum(ang_deg), count
__device__ unsigned int g_done;     // last-block-done counter

// ---------------------------------------------------------------------------
// 1 node/thread; loads coalesce across the warp, stores are 16B aligned.
__global__ void pack_kernel(const float* __restrict__ x,
                            const float* __restrict__ s,
                            int N) {
    int i = blockIdx.x * blockDim.x + threadIdx.x;
    if (i < N) {
        g_P[i] = make_float4(x[3 * i], x[3 * i + 1], x[3 * i + 2], s[i]);
        g_Z[i] = make_float4(0.f, 0.f, 0.f, 0.f);
    }
    if (i == 0) {
        g_acc[0] = 0.0; g_acc[1] = 0.0; g_acc[2] = 0.0;
        g_done = 0u;
    }
}

// ---------------------------------------------------------------------------
// 2 edges/thread, capped registers for 1536 threads/SM residency. (Unchanged.)
__global__ __launch_bounds__(256, 6)
void edge_kernel(const int* __restrict__ ei, int E) {
    int t = blockIdx.x * blockDim.x + threadIdx.x;
    int e0 = t * 2;
    if (e0 >= E) return;

    if (e0 + 2 <= E) {
        int2 av = *reinterpret_cast<const int2*>(ei + e0);
        int2 bv = *reinterpret_cast<const int2*>(ei + E + e0);

        // Issue all 4 gathers before any dependent math (MLP=4/thread).
        float4 Pa0 = __ldg(&g_P[av.x]);
        float4 Pb0 = __ldg(&g_P[bv.x]);
        float4 Pa1 = __ldg(&g_P[av.y]);
        float4 Pb1 = __ldg(&g_P[bv.y]);

        float ds0 = Pb0.w - Pa0.w;
        float c0x = (Pb0.x - Pa0.x) * ds0;
        float c0y = (Pb0.y - Pa0.y) * ds0;
        float c0z = (Pb0.z - Pa0.z) * ds0;
        float ds1 = Pb1.w - Pa1.w;
        float c1x = (Pb1.x - Pa1.x) * ds1;
        float c1y = (Pb1.y - Pa1.y) * ds1;
        float c1z = (Pb1.z - Pa1.z) * ds1;

        asm volatile("red.global.add.v4.f32 [%0], {%1, %2, %3, %4};"
                     :: "l"((float*)&g_Z[av.x]), "f"(c0x), "f"(c0y), "f"(c0z), "f"(0.0f) : "memory");
        asm volatile("red.global.add.v4.f32 [%0], {%1, %2, %3, %4};"
                     :: "l"((float*)&g_Z[bv.x]), "f"(c0x), "f"(c0y), "f"(c0z), "f"(0.0f) : "memory");
        asm volatile("red.global.add.v4.f32 [%0], {%1, %2, %3, %4};"
                     :: "l"((float*)&g_Z[av.y]), "f"(c1x), "f"(c1y), "f"(c1z), "f"(0.0f) : "memory");
        asm volatile("red.global.add.v4.f32 [%0], {%1, %2, %3, %4};"
                     :: "l"((float*)&g_Z[bv.y]), "f"(c1x), "f"(c1y), "f"(c1z), "f"(0.0f) : "memory");
    } else {
        for (int e = e0; e < E; e++) {
            int a = ei[e], b = ei[E + e];
            float4 Pa = __ldg(&g_P[a]);
            float4 Pb = __ldg(&g_P[b]);
            float ds = Pb.w - Pa.w;
            float cx = (Pb.x - Pa.x) * ds;
            float cy = (Pb.y - Pa.y) * ds;
            float cz = (Pb.z - Pa.z) * ds;
            asm volatile("red.global.add.v4.f32 [%0], {%1, %2, %3, %4};"
                         :: "l"((float*)&g_Z[a]), "f"(cx), "f"(cy), "f"(cz), "f"(0.0f) : "memory");
            asm volatile("red.global.add.v4.f32 [%0], {%1, %2, %3, %4};"
                         :: "l"((float*)&g_Z[b]), "f"(cx), "f"(cy), "f"(cz), "f"(0.0f) : "memory");
        }
    }
}

// ---------------------------------------------------------------------------
// 1 node/thread node reduction + fused finalize (last block writes outputs).
__global__ void node_kernel(const float* __restrict__ y,
                            const int* __restrict__ mask,
                            int N, float* __restrict__ out) {
    int i = blockIdx.x * blockDim.x + threadIdx.x;

    float l = 0.f, ang = 0.f, c = 0.f;
    if (i < N && mask[i] != 0) {
        float4 Z = g_Z[i];
        float y0 = y[3 * i], y1 = y[3 * i + 1], y2 = y[3 * i + 2];
        float dot = y0 * Z.x + y1 * Z.y + y2 * Z.z;
        float nz = sqrtf(Z.x * Z.x + Z.y * Z.y + Z.z * Z.z);
        float ny = sqrtf(y0 * y0 + y1 * y1 + y2 * y2);
        float cosv = dot / (ny * nz);
        l = 1.0f - fabsf(cosv);
        float cl = fminf(1.0f, fmaxf(-1.0f, cosv));
        ang = acosf(cl) * 57.295779513082320877f;  // degrees
        c = 1.0f;
    }

    #pragma unroll
    for (int o = 16; o > 0; o >>= 1) {
        l   += __shfl_down_sync(0xffffffffu, l,   o);
        ang += __shfl_down_sync(0xffffffffu, ang, o);
        c   += __shfl_down_sync(0xffffffffu, c,   o);
    }

    __shared__ float sl[4], sa_[4], sc[4];
    __shared__ bool is_last;
    int wid = threadIdx.x >> 5;
    int lid = threadIdx.x & 31;
    if (lid == 0) { sl[wid] = l; sa_[wid] = ang; sc[wid] = c; }
    __syncthreads();

    if (threadIdx.x == 0) {
        float bl = 0.f, ba = 0.f, bc = 0.f;
        int nwarp = (blockDim.x + 31) >> 5;
        for (int w = 0; w < nwarp; w++) { bl += sl[w]; ba += sa_[w]; bc += sc[w]; }
        atomicAdd(&g_acc[0], (double)bl);
        atomicAdd(&g_acc[1], (double)ba);
        atomicAdd(&g_acc[2], (double)bc);
        __threadfence();
        unsigned int done = atomicAdd(&g_done, 1u);
        is_last = (done == gridDim.x - 1);
    }
    __syncthreads();

    if (is_last && threadIdx.x == 0) {
        double cnt = g_acc[2];
        if (cnt < 1.0) cnt = 1.0;
        out[0] = (float)(g_acc[0] / cnt);
        out[1] = (float)(g_acc[1] / cnt);
    }
}

// ---------------------------------------------------------------------------
extern "C" void kernel_launch(void* const* d_in, const int* in_sizes, int n_in,
                              void* d_out, int out_size) {
    const float* x    = (const float*)d_in[0];   // [N,3]
    const float* y    = (const float*)d_in[1];   // [N,3]
    const float* s    = (const float*)d_in[2];   // [N]
    const int*   ei   = (const int*)d_in[3];     // [2,E] int32
    const int*   mask = (const int*)d_in[4];     // [N]   int32 (bool)
    float* out = (float*)d_out;

    int N = in_sizes[2];
    int E = in_sizes[3] / 2;

    // Helper kernels: 1 element/thread, TB=128 -> grid ~782 (full chip coverage).
    const int TBH = 128;
    pack_kernel<<<(N + TBH - 1) / TBH, TBH>>>(x, s, N);

    const int TB = 256;
    int nthreads = (E + 1) / 2;
    edge_kernel<<<(nthreads + TB - 1) / TB, TB>>>(ei, E);

    node_kernel<<<(N + TBH - 1) / TBH, TBH>>>(y, mask, N, out);
}

// round 9
// speedup vs baseline: 1.0306x; 1.0306x over previous
#include <cuda_runtime.h>
#include <cstdint>

// ---------------------------------------------------------------------------
// CustomOrientationLoss (R9):
//   pack:  (x,s) -> aligned float4 table, zero Z      [R7-best quad variant]
//   edge:  symmetric per-edge scatter via red.v4.f32  [1 edge/thr, occ 16 ->
//          2048 threads/SM: close the concurrency gap vs LTS throughput floor]
//   node:  cos/angle reduction + fused finalize       [R7-best quad variant]
// ---------------------------------------------------------------------------

#define NMAX 100000

__device__ float4 g_P[NMAX];        // (x0,x1,x2,s)
__device__ float4 g_Z[NMAX];        // accumulator (w unused)
__device__ double g_acc[3];         // sum(1-|cos|), sum(ang_deg), count
__device__ unsigned int g_done;     // last-block-done counter

// ---------------------------------------------------------------------------
__global__ void pack_kernel(const float* __restrict__ x,
                            const float* __restrict__ s,
                            int N) {
    int q = blockIdx.x * blockDim.x + threadIdx.x;   // node quad
    int nq = N >> 2;
    const float4* x4 = (const float4*)x;
    const float4* s4 = (const float4*)s;
    if (q < nq) {
        float4 a = x4[3 * q + 0];
        float4 b = x4[3 * q + 1];
        float4 c = x4[3 * q + 2];
        float4 sv = s4[q];
        int n0 = 4 * q;
        g_P[n0 + 0] = make_float4(a.x, a.y, a.z, sv.x);
        g_P[n0 + 1] = make_float4(a.w, b.x, b.y, sv.y);
        g_P[n0 + 2] = make_float4(b.z, b.w, c.x, sv.z);
        g_P[n0 + 3] = make_float4(c.y, c.z, c.w, sv.w);
        float4 z0 = make_float4(0.f, 0.f, 0.f, 0.f);
        g_Z[n0 + 0] = z0; g_Z[n0 + 1] = z0;
        g_Z[n0 + 2] = z0; g_Z[n0 + 3] = z0;
    }
    int rem = N - (nq << 2);
    if (q < rem) {
        int i = (nq << 2) + q;
        g_P[i] = make_float4(x[3 * i], x[3 * i + 1], x[3 * i + 2], s[i]);
        g_Z[i] = make_float4(0.f, 0.f, 0.f, 0.f);
    }
    if (q == 0) {
        g_acc[0] = 0.0; g_acc[1] = 0.0; g_acc[2] = 0.0;
        g_done = 0u;
    }
}

// ---------------------------------------------------------------------------
// 1 edge/thread, minimal registers, 2048 threads/SM residency.
__global__ __launch_bounds__(128, 16)
void edge_kernel(const int* __restrict__ ei, int E) {
    int e = blockIdx.x * blockDim.x + threadIdx.x;
    if (e >= E) return;

    int a = __ldg(ei + e);
    int b = __ldg(ei + E + e);

    float4 Pa = __ldg(&g_P[a]);
    float4 Pb = __ldg(&g_P[b]);

    float ds = Pb.w - Pa.w;
    float cx = (Pb.x - Pa.x) * ds;
    float cy = (Pb.y - Pa.y) * ds;
    float cz = (Pb.z - Pa.z) * ds;

    asm volatile("red.global.add.v4.f32 [%0], {%1, %2, %3, %4};"
                 :: "l"((float*)&g_Z[a]), "f"(cx), "f"(cy), "f"(cz), "f"(0.0f) : "memory");
    asm volatile("red.global.add.v4.f32 [%0], {%1, %2, %3, %4};"
                 :: "l"((float*)&g_Z[b]), "f"(cx), "f"(cy), "f"(cz), "f"(0.0f) : "memory");
}

// ---------------------------------------------------------------------------
// Node reduction (4 nodes/thread, vectorized) + fused finalize.
__global__ void node_kernel(const float* __restrict__ y,
                            const int* __restrict__ mask,
                            int N, float* __restrict__ out) {
    int q = blockIdx.x * blockDim.x + threadIdx.x;
    int nq = N >> 2;

    float l = 0.f, ang = 0.f, c = 0.f;
    const float4* y4 = (const float4*)y;
    const int4*   m4 = (const int4*)mask;

    if (q < nq) {
        float4 a = y4[3 * q + 0];
        float4 b = y4[3 * q + 1];
        float4 cc4 = y4[3 * q + 2];
        int4  mv = m4[q];
        int n0 = 4 * q;
        float yv[4][3] = {
            {a.x, a.y, a.z}, {a.w, b.x, b.y},
            {b.z, b.w, cc4.x}, {cc4.y, cc4.z, cc4.w}};
        int mm[4] = {mv.x, mv.y, mv.z, mv.w};
        #pragma unroll
        for (int k = 0; k < 4; k++) {
            if (mm[k] != 0) {
                float4 Z = g_Z[n0 + k];
                float dot = yv[k][0] * Z.x + yv[k][1] * Z.y + yv[k][2] * Z.z;
                float nz = sqrtf(Z.x * Z.x + Z.y * Z.y + Z.z * Z.z);
                float ny = sqrtf(yv[k][0] * yv[k][0] + yv[k][1] * yv[k][1] +
                                 yv[k][2] * yv[k][2]);
                float cosv = dot / (ny * nz);
                l += 1.0f - fabsf(cosv);
                float cl = fminf(1.0f, fmaxf(-1.0f, cosv));
                ang += acosf(cl) * 57.295779513082320877f;
                c += 1.0f;
            }
        }
    }
    int rem = N - (nq << 2);
    if (q < rem) {
        int i = (nq << 2) + q;
        if (mask[i] != 0) {
            float4 Z = g_Z[i];
            float y0 = y[3 * i], y1 = y[3 * i + 1], y2 = y[3 * i + 2];
            float dot = y0 * Z.x + y1 * Z.y + y2 * Z.z;
            float nz = sqrtf(Z.x * Z.x + Z.y * Z.y + Z.z * Z.z);
            float ny = sqrtf(y0 * y0 + y1 * y1 + y2 * y2);
            float cosv = dot / (ny * nz);
            l += 1.0f - fabsf(cosv);
            float cl = fminf(1.0f, fmaxf(-1.0f, cosv));
            ang += acosf(cl) * 57.295779513082320877f;
            c += 1.0f;
        }
    }

    #pragma unroll
    for (int o = 16; o > 0; o >>= 1) {
        l   += __shfl_down_sync(0xffffffffu, l,   o);
        ang += __shfl_down_sync(0xffffffffu, ang, o);
        c   += __shfl_down_sync(0xffffffffu, c,   o);
    }

    __shared__ float sl[8], sa_[8], sc[8];
    __shared__ bool is_last;
    int wid = threadIdx.x >> 5;
    int lid = threadIdx.x & 31;
    if (lid == 0) { sl[wid] = l; sa_[wid] = ang; sc[wid] = c; }
    __syncthreads();

    if (threadIdx.x == 0) {
        float bl = 0.f, ba = 0.f, bc = 0.f;
        int nwarp = (blockDim.x + 31) >> 5;
        for (int w = 0; w < nwarp; w++) { bl += sl[w]; ba += sa_[w]; bc += sc[w]; }
        atomicAdd(&g_acc[0], (double)bl);
        atomicAdd(&g_acc[1], (double)ba);
        atomicAdd(&g_acc[2], (double)bc);
        __threadfence();
        unsigned int done = atomicAdd(&g_done, 1u);
        is_last = (done == gridDim.x - 1);
    }
    __syncthreads();

    if (is_last && threadIdx.x == 0) {
        double cnt = g_acc[2];
        if (cnt < 1.0) cnt = 1.0;
        out[0] = (float)(g_acc[0] / cnt);
        out[1] = (float)(g_acc[1] / cnt);
    }
}

// ---------------------------------------------------------------------------
extern "C" void kernel_launch(void* const* d_in, const int* in_sizes, int n_in,
                              void* d_out, int out_size) {
    const float* x    = (const float*)d_in[0];   // [N,3]
    const float* y    = (const float*)d_in[1];   // [N,3]
    const float* s    = (const float*)d_in[2];   // [N]
    const int*   ei   = (const int*)d_in[3];     // [2,E] int32
    const int*   mask = (const int*)d_in[4];     // [N]   int32 (bool)
    float* out = (float*)d_out;

    int N = in_sizes[2];
    int E = in_sizes[3] / 2;

    const int TB = 256;
    int nq = (N + 3) / 4;
    pack_kernel<<<(nq + TB - 1) / TB, TB>>>(x, s, N);

    const int TBE = 128;
    edge_kernel<<<(E + TBE - 1) / TBE, TBE>>>(ei, E);

    node_kernel<<<(nq + TB - 1) / TB, TB>>>(y, mask, N, out);
}

// round 10
// speedup vs baseline: 1.0312x; 1.0005x over previous
#include <cuda_runtime.h>
#include <cstdint>

// ---------------------------------------------------------------------------
// CustomOrientationLoss (R10):
//   Same three phases as R9 (edge phase proven LTS-sector-throughput-bound at
//   ~52us across occ 6..16). New: PDL (programmatic dependent launch) so
//   edge overlaps pack (index loads need no pack output) and node overlaps
//   edge tail (y/mask prefetch needs no Z).
// ---------------------------------------------------------------------------

#define NMAX 100000

__device__ float4 g_P[NMAX];        // (x0,x1,x2,s)
__device__ float4 g_Z[NMAX];        // accumulator (w unused)
__device__ double g_acc[3];         // sum(1-|cos|), sum(ang_deg), count
__device__ unsigned int g_done;     // last-block-done counter

// ---------------------------------------------------------------------------
__global__ void pack_kernel(const float* __restrict__ x,
                            const float* __restrict__ s,
                            int N) {
    int q = blockIdx.x * blockDim.x + threadIdx.x;   // node quad
    int nq = N >> 2;
    const float4* x4 = (const float4*)x;
    const float4* s4 = (const float4*)s;
    if (q < nq) {
        float4 a = x4[3 * q + 0];
        float4 b = x4[3 * q + 1];
        float4 c = x4[3 * q + 2];
        float4 sv = s4[q];
        int n0 = 4 * q;
        g_P[n0 + 0] = make_float4(a.x, a.y, a.z, sv.x);
        g_P[n0 + 1] = make_float4(a.w, b.x, b.y, sv.y);
        g_P[n0 + 2] = make_float4(b.z, b.w, c.x, sv.z);
        g_P[n0 + 3] = make_float4(c.y, c.z, c.w, sv.w);
        float4 z0 = make_float4(0.f, 0.f, 0.f, 0.f);
        g_Z[n0 + 0] = z0; g_Z[n0 + 1] = z0;
        g_Z[n0 + 2] = z0; g_Z[n0 + 3] = z0;
    }
    int rem = N - (nq << 2);
    if (q < rem) {
        int i = (nq << 2) + q;
        g_P[i] = make_float4(x[3 * i], x[3 * i + 1], x[3 * i + 2], s[i]);
        g_Z[i] = make_float4(0.f, 0.f, 0.f, 0.f);
    }
    if (q == 0) {
        g_acc[0] = 0.0; g_acc[1] = 0.0; g_acc[2] = 0.0;
        g_done = 0u;
    }
}

// ---------------------------------------------------------------------------
// 1 edge/thread, occ 16. PDL: index loads overlap pack; sync before g_P/g_Z.
__global__ __launch_bounds__(128, 16)
void edge_kernel(const int* __restrict__ ei, int E) {
    int e = blockIdx.x * blockDim.x + threadIdx.x;
    bool valid = (e < E);
    int a = 0, b = 0;
    if (valid) {                       // independent prologue (pre-sync)
        a = __ldg(ei + e);
        b = __ldg(ei + E + e);
    }

    cudaGridDependencySynchronize();             // wait for pack's g_P / g_Z
    cudaTriggerProgrammaticLaunchCompletion();   // let node launch + prefetch

    if (!valid) return;

    float4 Pa = __ldg(&g_P[a]);
    float4 Pb = __ldg(&g_P[b]);

    float ds = Pb.w - Pa.w;
    float cx = (Pb.x - Pa.x) * ds;
    float cy = (Pb.y - Pa.y) * ds;
    float cz = (Pb.z - Pa.z) * ds;

    asm volatile("red.global.add.v4.f32 [%0], {%1, %2, %3, %4};"
                 :: "l"((float*)&g_Z[a]), "f"(cx), "f"(cy), "f"(cz), "f"(0.0f) : "memory");
    asm volatile("red.global.add.v4.f32 [%0], {%1, %2, %3, %4};"
                 :: "l"((float*)&g_Z[b]), "f"(cx), "f"(cy), "f"(cz), "f"(0.0f) : "memory");
}

// ---------------------------------------------------------------------------
// Node reduction + fused finalize. PDL: y/mask prefetch pre-sync, Z post-sync.
__global__ void node_kernel(const float* __restrict__ y,
                            const int* __restrict__ mask,
                            int N, float* __restrict__ out) {
    int q = blockIdx.x * blockDim.x + threadIdx.x;
    int nq = N >> 2;

    const float4* y4 = (const float4*)y;
    const int4*   m4 = (const int4*)mask;

    // ---- independent prologue: stream y + mask while edge finishes ----
    float4 a = {}, b = {}, cc4 = {};
    int4 mv = {};
    bool inq = (q < nq);
    if (inq) {
        a   = y4[3 * q + 0];
        b   = y4[3 * q + 1];
        cc4 = y4[3 * q + 2];
        mv  = m4[q];
    }

    cudaGridDependencySynchronize();   // wait for edge's g_Z REDs

    float l = 0.f, ang = 0.f, c = 0.f;
    if (inq) {
        int n0 = 4 * q;
        float yv[4][3] = {
            {a.x, a.y, a.z}, {a.w, b.x, b.y},
            {b.z, b.w, cc4.x}, {cc4.y, cc4.z, cc4.w}};
        int mm[4] = {mv.x, mv.y, mv.z, mv.w};
        #pragma unroll
        for (int k = 0; k < 4; k++) {
            if (mm[k] != 0) {
                float4 Z = g_Z[n0 + k];
                float dot = yv[k][0] * Z.x + yv[k][1] * Z.y + yv[k][2] * Z.z;
                float nz = sqrtf(Z.x * Z.x + Z.y * Z.y + Z.z * Z.z);
                float ny = sqrtf(yv[k][0] * yv[k][0] + yv[k][1] * yv[k][1] +
                                 yv[k][2] * yv[k][2]);
                float cosv = dot / (ny * nz);
                l += 1.0f - fabsf(cosv);
                float cl = fminf(1.0f, fmaxf(-1.0f, cosv));
                ang += acosf(cl) * 57.295779513082320877f;
                c += 1.0f;
            }
        }
    }
    int rem = N - (nq << 2);
    if (q < rem) {
        int i = (nq << 2) + q;
        if (mask[i] != 0) {
            float4 Z = g_Z[i];
            float y0 = y[3 * i], y1 = y[3 * i + 1], y2 = y[3 * i + 2];
            float dot = y0 * Z.x + y1 * Z.y + y2 * Z.z;
            float nz = sqrtf(Z.x * Z.x + Z.y * Z.y + Z.z * Z.z);
            float ny = sqrtf(y0 * y0 + y1 * y1 + y2 * y2);
            float cosv = dot / (ny * nz);
            l += 1.0f - fabsf(cosv);
            float cl = fminf(1.0f, fmaxf(-1.0f, cosv));
            ang += acosf(cl) * 57.295779513082320877f;
            c += 1.0f;
        }
    }

    #pragma unroll
    for (int o = 16; o > 0; o >>= 1) {
        l   += __shfl_down_sync(0xffffffffu, l,   o);
        ang += __shfl_down_sync(0xffffffffu, ang, o);
        c   += __shfl_down_sync(0xffffffffu, c,   o);
    }

    __shared__ float sl[8], sa_[8], sc[8];
    __shared__ bool is_last;
    int wid = threadIdx.x >> 5;
    int lid = threadIdx.x & 31;
    if (lid == 0) { sl[wid] = l; sa_[wid] = ang; sc[wid] = c; }
    __syncthreads();

    if (threadIdx.x == 0) {
        float bl = 0.f, ba = 0.f, bc = 0.f;
        int nwarp = (blockDim.x + 31) >> 5;
        for (int w = 0; w < nwarp; w++) { bl += sl[w]; ba += sa_[w]; bc += sc[w]; }
        atomicAdd(&g_acc[0], (double)bl);
        atomicAdd(&g_acc[1], (double)ba);
        atomicAdd(&g_acc[2], (double)bc);
        __threadfence();
        unsigned int done = atomicAdd(&g_done, 1u);
        is_last = (done == gridDim.x - 1);
    }
    __syncthreads();

    if (is_last && threadIdx.x == 0) {
        double cnt = g_acc[2];
        if (cnt < 1.0) cnt = 1.0;
        out[0] = (float)(g_acc[0] / cnt);
        out[1] = (float)(g_acc[1] / cnt);
    }
}

// ---------------------------------------------------------------------------
static void launch_with_pdl(const void* func, dim3 grid, dim3 block, void** args) {
    cudaLaunchConfig_t cfg = {};
    cfg.gridDim = grid;
    cfg.blockDim = block;
    cfg.dynamicSmemBytes = 0;
    cfg.stream = 0;   // same (captured) default stream as <<<>>> launches
    cudaLaunchAttribute attr[1];
    attr[0].id = cudaLaunchAttributeProgrammaticStreamSerialization;
    attr[0].val.programmaticStreamSerializationAllowed = 1;
    cfg.attrs = attr;
    cfg.numAttrs = 1;
    cudaLaunchKernelExC(&cfg, func, args);
}

extern "C" void kernel_launch(void* const* d_in, const int* in_sizes, int n_in,
                              void* d_out, int out_size) {
    const float* x    = (const float*)d_in[0];   // [N,3]
    const float* y    = (const float*)d_in[1];   // [N,3]
    const float* s    = (const float*)d_in[2];   // [N]
    const int*   ei   = (const int*)d_in[3];     // [2,E] int32
    const int*   mask = (const int*)d_in[4];     // [N]   int32 (bool)
    float* out = (float*)d_out;

    int N = in_sizes[2];
    int E = in_sizes[3] / 2;

    const int TB = 256;
    int nq = (N + 3) / 4;
    pack_kernel<<<(nq + TB - 1) / TB, TB>>>(x, s, N);

    const int TBE = 128;
    {
        void* args[] = { (void*)&ei, (void*)&E };
        launch_with_pdl((const void*)edge_kernel,
                        dim3((E + TBE - 1) / TBE), dim3(TBE), args);
    }
    {
        void* args[] = { (void*)&y, (void*)&mask, (void*)&N, (void*)&out };
        launch_with_pdl((const void*)node_kernel,
                        dim3((nq + TB - 1) / TB), dim3(TB), args);
    }
}